// round 2
// baseline (speedup 1.0000x reference)
#include <cuda_runtime.h>
#include <cstdint>

typedef unsigned long long ull;

// Problem constants (fixed by the reference).
#define NP    16384
#define FIN   64
#define MC    4096
#define KN    64
#define FH    64
#define FO    128
#define FD    67
#define FPAD  68
#define R2F   0.04f

#define NLEAF 512
#define LSZ   32

// Scratch (static __device__ — no allocations allowed).
__device__ int   g_idx[MC];
__device__ float g_pos_s[MC * 3];
__device__ int   g_nbr[MC * KN];
__device__ int   g_cnt[MC];
// FPS structure
__device__ float g_px[NP], g_py[NP], g_pz[NP];   // Morton-reordered coords
__device__ int   g_orig[NP];                     // reordered -> original idx
__device__ float g_axlo[NLEAF], g_axhi[NLEAF], g_aylo[NLEAF],
                 g_ayhi[NLEAF], g_azlo[NLEAF], g_azhi[NLEAF];

// ---------------------------------------------------------------------------
// 0) Build: Morton sort (bitonic, one CTA) -> reordered coords + leaf AABBs.
// ---------------------------------------------------------------------------
__device__ __forceinline__ unsigned expand10(unsigned v) {
    v &= 1023u;
    v = (v | (v << 16)) & 0x030000FFu;
    v = (v | (v << 8))  & 0x0300F00Fu;
    v = (v | (v << 4))  & 0x030C30C3u;
    v = (v | (v << 2))  & 0x09249249u;
    return v;
}

#define BLD_T 512
#define BLD_SMEM (NP * 8)

__global__ __launch_bounds__(BLD_T) void build_kernel(const float* __restrict__ pos)
{
    extern __shared__ ull sk[];
    int t = threadIdx.x;

    for (int i = t; i < NP; i += BLD_T) {
        float x = pos[3 * i + 0], y = pos[3 * i + 1], z = pos[3 * i + 2];
        unsigned ux = (unsigned)fminf(1023.f, fmaxf(0.f, (x + 5.12f) * 100.0f));
        unsigned uy = (unsigned)fminf(1023.f, fmaxf(0.f, (y + 5.12f) * 100.0f));
        unsigned uz = (unsigned)fminf(1023.f, fmaxf(0.f, (z + 5.12f) * 100.0f));
        unsigned code = (expand10(ux) << 2) | (expand10(uy) << 1) | expand10(uz);
        sk[i] = ((ull)code << 32) | (unsigned)i;
    }
    __syncthreads();

    for (unsigned k2 = 2; k2 <= NP; k2 <<= 1) {
        for (unsigned j = k2 >> 1; j > 0; j >>= 1) {
            for (unsigned i = t; i < NP; i += BLD_T) {
                unsigned ixj = i ^ j;
                if (ixj > i) {
                    ull a = sk[i], b = sk[ixj];
                    bool up = ((i & k2) == 0);
                    if ((a > b) == up) { sk[i] = b; sk[ixj] = a; }
                }
            }
            __syncthreads();
        }
    }

    for (int i = t; i < NP; i += BLD_T) {
        unsigned idx = (unsigned)sk[i];
        g_px[i] = pos[3 * idx + 0];
        g_py[i] = pos[3 * idx + 1];
        g_pz[i] = pos[3 * idx + 2];
        g_orig[i] = (int)idx;
    }
    __syncthreads();

    // One thread per leaf: tight AABB (global writes above visible after sync).
    {
        int l = t;
        float xl = 1e30f, xh = -1e30f, yl = 1e30f, yh = -1e30f, zl = 1e30f, zh = -1e30f;
#pragma unroll 8
        for (int m = 0; m < LSZ; m++) {
            int p = l * LSZ + m;
            float x = g_px[p], y = g_py[p], z = g_pz[p];
            xl = fminf(xl, x); xh = fmaxf(xh, x);
            yl = fminf(yl, y); yh = fmaxf(yh, y);
            zl = fminf(zl, z); zh = fmaxf(zh, z);
        }
        g_axlo[l] = xl; g_axhi[l] = xh;
        g_aylo[l] = yl; g_ayhi[l] = yh;
        g_azlo[l] = zl; g_azhi[l] = zh;
    }
}

// ---------------------------------------------------------------------------
// 1) FPS with leaf pruning — single persistent CTA.
//    Per-point packed key (f32bits(min_d2)<<32 | ~orig_idx) in smem; per-leaf
//    cached max key; leaves whose AABB lower bound >= leaf max are skipped
//    (value-preserving => bit-identical to dense FPS).
// ---------------------------------------------------------------------------
#define FPS_T 512
#define FPS_NW (FPS_T / 32)

#define SOFF_PK   0
#define SOFF_KEY  (SOFF_PK  + NP * 8)
#define SOFF_AX   (SOFF_KEY + NLEAF * 8)
#define SOFF_DRT  (SOFF_AX  + NLEAF * 6 * 4)
#define SOFF_MISC (SOFF_DRT + NLEAF * 4)
#define FPS_SMEM  (SOFF_MISC + 64)

__global__ __launch_bounds__(FPS_T) void fps_kernel(const float* __restrict__ pos)
{
    extern __shared__ unsigned char smem_raw[];
    ull*   s_pk   = (ull*)(smem_raw + SOFF_PK);                 // [NP]
    ull*   s_key  = (ull*)(smem_raw + SOFF_KEY);                // [NLEAF]
    float* s_xlo  = (float*)(smem_raw + SOFF_AX);
    float* s_xhi  = s_xlo + NLEAF;
    float* s_ylo  = s_xhi + NLEAF;
    float* s_yhi  = s_ylo + NLEAF;
    float* s_zlo  = s_yhi + NLEAF;
    float* s_zhi  = s_zlo + NLEAF;
    int*   s_drt  = (int*)(smem_raw + SOFF_DRT);                // [NLEAF]
    float* s_q    = (float*)(smem_raw + SOFF_MISC);             // [3]
    ull*   s_gk   = (ull*)(smem_raw + SOFF_MISC + 16);          // [2]
    int*   s_cnt  = (int*)(smem_raw + SOFF_MISC + 32);

    int t = threadIdx.x;
    int w = t >> 5, lane = t & 31;

    // Init
    for (int p = t; p < NP; p += FPS_T)
        s_pk[p] = (0x7f800000ull << 32) | (ull)(0xFFFFFFFFu - (unsigned)g_orig[p]);
    {
        int l = t;   // NLEAF == FPS_T
        s_key[l] = (0x7f800000ull << 32);
        s_xlo[l] = g_axlo[l]; s_xhi[l] = g_axhi[l];
        s_ylo[l] = g_aylo[l]; s_yhi[l] = g_ayhi[l];
        s_zlo[l] = g_azlo[l]; s_zhi[l] = g_azhi[l];
    }
    if (t == 0) {
        g_idx[0] = 0;
        s_q[0] = pos[0]; s_q[1] = pos[1]; s_q[2] = pos[2];
        s_gk[0] = 0ull; s_gk[1] = 0ull;
        *s_cnt = 0;
    }
    __syncthreads();

    for (int it = 1; it < MC; it++) {
        float qx = s_q[0], qy = s_q[1], qz = s_q[2];

        // Phase 1: mark dirty leaves (lb < cached leaf max)
        {
            int l = t;
            float ddx = fmaxf(fmaxf(s_xlo[l] - qx, qx - s_xhi[l]), 0.0f);
            float ddy = fmaxf(fmaxf(s_ylo[l] - qy, qy - s_yhi[l]), 0.0f);
            float ddz = fmaxf(fmaxf(s_zlo[l] - qz, qz - s_zhi[l]), 0.0f);
            float lb = (ddx * ddx + ddy * ddy + ddz * ddz) * 0.9999f;
            unsigned lm = (unsigned)(s_key[l] >> 32);
            if (__float_as_uint(lb) < lm) {
                int n = atomicAdd(s_cnt, 1);
                s_drt[n] = l;
            }
        }
        __syncthreads();

        // Phase 2: one warp per dirty leaf; update packed keys + leaf max
        int D = *s_cnt;
        for (int d = w; d < D; d += FPS_NW) {
            int l = s_drt[d];
            int p = (l << 5) + lane;
            ull k = s_pk[p];
            float dx = __fadd_rn(g_px[p], -qx);
            float dy = __fadd_rn(g_py[p], -qy);
            float dz = __fadd_rn(g_pz[p], -qz);
            float d2 = __fmaf_rn(dz, dz, __fmaf_rn(dy, dy, __fmul_rn(dx, dx)));
            unsigned hi = (unsigned)(k >> 32);
            unsigned nd = __float_as_uint(d2);     // d2 >= 0: bit order == float order
            if (nd < hi) {
                k = ((ull)nd << 32) | (unsigned)k;
                s_pk[p] = k;
            }
#pragma unroll
            for (int o = 16; o > 0; o >>= 1) {
                ull ok = __shfl_xor_sync(0xFFFFFFFFu, k, o);
                if (ok > k) k = ok;
            }
            if (lane == 0) s_key[l] = k;
        }
        __syncthreads();

        // Phase 3: global argmax over leaf keys
        {
            ull k = s_key[t];
#pragma unroll
            for (int o = 16; o > 0; o >>= 1) {
                ull ok = __shfl_xor_sync(0xFFFFFFFFu, k, o);
                if (ok > k) k = ok;
            }
            int slot = it & 1;
            if (lane == 0) atomicMax(&s_gk[slot], k);
            __syncthreads();
            ull gk = s_gk[slot];
            unsigned nxt = 0xFFFFFFFFu - (unsigned)gk;
            if (t == 0) {
                g_idx[it] = (int)nxt;
                s_gk[slot ^ 1] = 0ull;
                *s_cnt = 0;
            }
            if (t < 3) s_q[t] = pos[3 * nxt + t];
        }
        __syncthreads();
    }
}

// ---------------------------------------------------------------------------
// 2) Gather sampled positions (+ tuple tail if flattened output).
// ---------------------------------------------------------------------------
__global__ void gather_kernel(const float* __restrict__ pos, float* __restrict__ out, int out_size)
{
    int c = blockIdx.x * blockDim.x + threadIdx.x;
    if (c >= MC) return;
    int j = g_idx[c];
    float x = pos[3 * j + 0], y = pos[3 * j + 1], z = pos[3 * j + 2];
    g_pos_s[3 * c + 0] = x; g_pos_s[3 * c + 1] = y; g_pos_s[3 * c + 2] = z;
    int base = MC * FO;
    if (out_size >= base + 3 * MC) {
        out[base + 3 * c + 0] = x; out[base + 3 * c + 1] = y; out[base + 3 * c + 2] = z;
    }
    if (out_size >= base + 4 * MC) out[base + 3 * MC + c] = 0.0f;
}

// ---------------------------------------------------------------------------
// 3) Radius neighbors (unchanged, passing).
// ---------------------------------------------------------------------------
#define RB_C   16
#define RB_T   256
#define RB_CAP 192

__global__ __launch_bounds__(RB_T) void radius_kernel(const float* __restrict__ pos)
{
    __shared__ float scx[RB_C], scy[RB_C], scz[RB_C];
    __shared__ int   scnt[RB_C];
    __shared__ int   sidx[RB_C][RB_CAP];
    __shared__ float sd2[RB_C][RB_CAP];

    int t = threadIdx.x;
    int c0 = blockIdx.x * RB_C;
    if (t < RB_C) {
        scx[t] = g_pos_s[3 * (c0 + t) + 0];
        scy[t] = g_pos_s[3 * (c0 + t) + 1];
        scz[t] = g_pos_s[3 * (c0 + t) + 2];
        scnt[t] = 0;
    }
    __syncthreads();

    for (int j = t; j < NP; j += RB_T) {
        float x = pos[3 * j + 0], y = pos[3 * j + 1], z = pos[3 * j + 2];
#pragma unroll
        for (int c = 0; c < RB_C; c++) {
            float dx = __fadd_rn(scx[c], -x);
            float dy = __fadd_rn(scy[c], -y);
            float dz = __fadd_rn(scz[c], -z);
            float d2 = __fmaf_rn(dz, dz, __fmaf_rn(dy, dy, __fmul_rn(dx, dx)));
            if (d2 <= R2F) {
                int n = atomicAdd(&scnt[c], 1);
                if (n < RB_CAP) { sidx[c][n] = j; sd2[c][n] = d2; }
            }
        }
    }
    __syncthreads();

    for (int c = 0; c < RB_C; c++) {
        int cnt = min(scnt[c], RB_CAP);
        int cg = c0 + c;
        if (cnt <= KN) {
            if (t < cnt) g_nbr[cg * KN + t] = sidx[c][t];
            if (t == 0)  g_cnt[cg] = cnt;
        } else {
            for (int i = t; i < cnt; i += RB_T) {
                float di = sd2[c][i]; int ii = sidx[c][i];
                int rank = 0;
                for (int jj = 0; jj < cnt; jj++) {
                    float dj = sd2[c][jj];
                    rank += (dj < di) || (dj == di && sidx[c][jj] < ii);
                }
                if (rank < KN) g_nbr[cg * KN + rank] = ii;
            }
            if (t == 0) g_cnt[cg] = KN;
        }
    }
}

// ---------------------------------------------------------------------------
// 4) Per-edge MLP + max-pool (unchanged, passing).
// ---------------------------------------------------------------------------
#define ML_T    256
#define ML_GRID 304

#define OFF_W1 0
#define OFF_W2 (OFF_W1 + FD * FH)
#define OFF_W3 (OFF_W2 + FH * FH)
#define OFF_B1 (OFF_W3 + FH * FO)
#define OFF_B2 (OFF_B1 + FH)
#define OFF_B3 (OFF_B2 + FH)
#define OFF_F  (OFF_B3 + FO)
#define OFF_H  (OFF_F + KN * FPAD)
#define OFF_O  (OFF_H + KN * FPAD)
#define ML_SMEM ((OFF_O + FO) * 4)

__global__ __launch_bounds__(ML_T, 2) void mlp_kernel(
    const float* __restrict__ x, const float* __restrict__ pos,
    const float* __restrict__ W1, const float* __restrict__ b1,
    const float* __restrict__ W2, const float* __restrict__ b2,
    const float* __restrict__ W3, const float* __restrict__ b3,
    float* __restrict__ out)
{
    extern __shared__ float sm[];
    float* sW1 = sm + OFF_W1;
    float* sW2 = sm + OFF_W2;
    float* sW3 = sm + OFF_W3;
    float* sb1 = sm + OFF_B1;
    float* sb2 = sm + OFF_B2;
    float* sb3 = sm + OFF_B3;
    float* sF  = sm + OFF_F;
    float* sH  = sm + OFF_H;
    int*   sO  = (int*)(sm + OFF_O);

    int t = threadIdx.x;
    for (int i = t; i < FD * FH; i += ML_T) sW1[i] = W1[i];
    for (int i = t; i < FH * FH; i += ML_T) sW2[i] = W2[i];
    for (int i = t; i < FH * FO; i += ML_T) sW3[i] = W3[i];
    if (t < FH) { sb1[t] = b1[t]; sb2[t] = b2[t]; }
    if (t < FO) sb3[t] = b3[t];

    int ei = t >> 4, ci = t & 15;

    for (int c = blockIdx.x; c < MC; c += gridDim.x) {
        __syncthreads();
        if (t < FO) sO[t] = 0;
        int E = g_cnt[c];
        float cx = g_pos_s[3 * c + 0], cy = g_pos_s[3 * c + 1], cz = g_pos_s[3 * c + 2];

        {
            int e = t >> 2, q = t & 3;
            if (e < E) {
                int nb = g_nbr[c * KN + e];
                const float4* xr = (const float4*)(x + (size_t)nb * FIN);
                float4* dst = (float4*)(sF + e * FPAD + q * 16);
                dst[0] = xr[q * 4 + 0]; dst[1] = xr[q * 4 + 1];
                dst[2] = xr[q * 4 + 2]; dst[3] = xr[q * 4 + 3];
                if (q == 0) {
                    sF[e * FPAD + 64] = pos[3 * nb + 0] - cx;
                    sF[e * FPAD + 65] = pos[3 * nb + 1] - cy;
                    sF[e * FPAD + 66] = pos[3 * nb + 2] - cz;
                    sF[e * FPAD + 67] = 0.0f;
                }
            }
        }
        __syncthreads();
        int ET = (E + 3) >> 2;

        if (ei < ET) {
            float acc[4][4];
#pragma unroll
            for (int j = 0; j < 4; j++)
#pragma unroll
                for (int a = 0; a < 4; a++) acc[j][a] = sb1[ci * 4 + a];
#pragma unroll 4
            for (int k = 0; k < FD; k++) {
                float4 wv = *(const float4*)(sW1 + k * FH + ci * 4);
                float f[4];
#pragma unroll
                for (int j = 0; j < 4; j++) f[j] = sF[(4 * ei + j) * FPAD + k];
#pragma unroll
                for (int j = 0; j < 4; j++) {
                    acc[j][0] += f[j] * wv.x; acc[j][1] += f[j] * wv.y;
                    acc[j][2] += f[j] * wv.z; acc[j][3] += f[j] * wv.w;
                }
            }
#pragma unroll
            for (int j = 0; j < 4; j++)
#pragma unroll
                for (int a = 0; a < 4; a++)
                    sH[(4 * ei + j) * FPAD + ci * 4 + a] = fmaxf(acc[j][a], 0.0f);
        }
        __syncthreads();

        if (ei < ET) {
            float acc[4][4];
#pragma unroll
            for (int j = 0; j < 4; j++)
#pragma unroll
                for (int a = 0; a < 4; a++) acc[j][a] = sb2[ci * 4 + a];
#pragma unroll 4
            for (int k = 0; k < FH; k++) {
                float4 wv = *(const float4*)(sW2 + k * FH + ci * 4);
                float f[4];
#pragma unroll
                for (int j = 0; j < 4; j++) f[j] = sH[(4 * ei + j) * FPAD + k];
#pragma unroll
                for (int j = 0; j < 4; j++) {
                    acc[j][0] += f[j] * wv.x; acc[j][1] += f[j] * wv.y;
                    acc[j][2] += f[j] * wv.z; acc[j][3] += f[j] * wv.w;
                }
            }
#pragma unroll
            for (int j = 0; j < 4; j++)
#pragma unroll
                for (int a = 0; a < 4; a++)
                    sF[(4 * ei + j) * FPAD + ci * 4 + a] = fmaxf(acc[j][a], 0.0f);
        }
        __syncthreads();

        if (ei < ET) {
            float acc[4][8];
#pragma unroll
            for (int j = 0; j < 4; j++)
#pragma unroll
                for (int a = 0; a < 8; a++) acc[j][a] = sb3[ci * 8 + a];
#pragma unroll 4
            for (int k = 0; k < FH; k++) {
                float4 wa = *(const float4*)(sW3 + k * FO + ci * 8);
                float4 wb = *(const float4*)(sW3 + k * FO + ci * 8 + 4);
                float f[4];
#pragma unroll
                for (int j = 0; j < 4; j++) f[j] = sF[(4 * ei + j) * FPAD + k];
#pragma unroll
                for (int j = 0; j < 4; j++) {
                    acc[j][0] += f[j] * wa.x; acc[j][1] += f[j] * wa.y;
                    acc[j][2] += f[j] * wa.z; acc[j][3] += f[j] * wa.w;
                    acc[j][4] += f[j] * wb.x; acc[j][5] += f[j] * wb.y;
                    acc[j][6] += f[j] * wb.z; acc[j][7] += f[j] * wb.w;
                }
            }
#pragma unroll
            for (int a = 0; a < 8; a++) {
                float mv = -1.0f;
#pragma unroll
                for (int j = 0; j < 4; j++)
                    if (4 * ei + j < E) mv = fmaxf(mv, fmaxf(acc[j][a], 0.0f));
                if (mv >= 0.0f) atomicMax(&sO[ci * 8 + a], __float_as_int(mv));
            }
        }
        __syncthreads();
        if (t < FO) out[(size_t)c * FO + t] = __int_as_float(sO[t]);
    }
}

// ---------------------------------------------------------------------------
extern "C" void kernel_launch(void* const* d_in, const int* in_sizes, int n_in,
                              void* d_out, int out_size)
{
    const float* x   = (const float*)d_in[0];
    const float* pos = (const float*)d_in[1];
    const float* W1 = (const float*)d_in[3];
    const float* b1 = (const float*)d_in[4];
    const float* W2 = (const float*)d_in[5];
    const float* b2 = (const float*)d_in[6];
    const float* W3 = (const float*)d_in[7];
    const float* b3 = (const float*)d_in[8];
    float* out = (float*)d_out;

    cudaFuncSetAttribute(build_kernel, cudaFuncAttributeMaxDynamicSharedMemorySize, BLD_SMEM);
    cudaFuncSetAttribute(fps_kernel,   cudaFuncAttributeMaxDynamicSharedMemorySize, FPS_SMEM);
    cudaFuncSetAttribute(mlp_kernel,   cudaFuncAttributeMaxDynamicSharedMemorySize, ML_SMEM);

    build_kernel<<<1, BLD_T, BLD_SMEM>>>(pos);
    fps_kernel<<<1, FPS_T, FPS_SMEM>>>(pos);
    gather_kernel<<<(MC + 255) / 256, 256>>>(pos, out, out_size);
    radius_kernel<<<MC / RB_C, RB_T>>>(pos);
    mlp_kernel<<<ML_GRID, ML_T, ML_SMEM>>>(x, pos, W1, b1, W2, b2, W3, b3, out);
}